// round 12
// baseline (speedup 1.0000x reference)
#include <cuda_runtime.h>
#include <cuda_bf16.h>
#include <math.h>
#include <stdint.h>

// Problem constants
#define BB 4
#define NN 100
#define TT 20
#define HH 64
#define OO 128
#define MM 40000            // B*N*N edges
#define NE 16               // edges per group
#define NGROUPS (MM/NE)     // 2500
#define ESLOT 22            // [0]=left pad, [1..20]=t, [21]=right pad
#define XR 360              // row stride words (==8 mod 32, conflict-free gathers)
#define PS 36               // efa_p per-edge stride
#define NTHREADS 256
#define NBLOCKS 296         // 2 CTAs per SM

// Scratch
__device__ float g_efa[MM * HH];   // 10.24 MB
__device__ float g_score[MM];
__device__ float g_attw[MM];
__device__ float g_A1[HH * 3];
__device__ float g_Bb[HH * 3];

// ---- helpers ---------------------------------------------------------------
__device__ __forceinline__ float tanha(float x) {
    float y;
    asm("tanh.approx.f32 %0, %1;" : "=f"(y) : "f"(x));
    return y;
}
__device__ __forceinline__ uint32_t pkbf2(float lo, float hi) {
    uint32_t r;
    asm("cvt.rn.bf16x2.f32 %0, %1, %2;" : "=r"(r) : "f"(hi), "f"(lo));
    return r;
}
__device__ __forceinline__ float bfu_lo(uint32_t w) {
    return __uint_as_float(w << 16);
}
__device__ __forceinline__ float bfu_hi(uint32_t w) {
    return __uint_as_float(w & 0xffff0000u);
}
__device__ __forceinline__ void mma_bf16(float d[4], uint4 a,
                                         uint32_t b0, uint32_t b1) {
    asm volatile(
        "mma.sync.aligned.m16n8k16.row.col.f32.bf16.bf16.f32 "
        "{%0,%1,%2,%3},{%4,%5,%6,%7},{%8,%9},{%0,%1,%2,%3};"
        : "+f"(d[0]), "+f"(d[1]), "+f"(d[2]), "+f"(d[3])
        : "r"(a.x), "r"(a.y), "r"(a.z), "r"(a.w), "r"(b0), "r"(b1));
}
#define HALF_BAR(id) \
    asm volatile("bar.sync %0, %1;" :: "r"(id), "r"(128) : "memory")

// ---------------------------------------------------------------------------
// K0: fold conv1 weights against the rank-1 edge embedding
// ---------------------------------------------------------------------------
__global__ void k_prep(const float* __restrict__ w1,
                       const float* __restrict__ We,
                       const float* __restrict__ be) {
    int idx = threadIdx.x;
    if (idx < HH * 3) {
        int h = idx / 3, k = idx % 3;
        float a = 0.f, c = 0.f;
        for (int i = 0; i < HH; ++i) {
            float w = w1[(h * HH + i) * 3 + k];
            a += w * We[i];
            c += w * be[i];
        }
        g_A1[idx] = a;
        g_Bb[idx] = c;
    }
}

// ---------------------------------------------------------------------------
// K2: fused pipeline; NE=16 per group, 256 threads, 2 CTAs/SM.
// CTA barriers only after x1 / Wt1+spart / softmax+efa / spatial; conv2<->epi
// WAR handled by per-half named barriers. Window-relative residue LUT.
// SMEM word offsets:
#define S_W2F   0           // 6144 : conv2 A-frags (bf16x2)
#define S_WT1F  6144        // 2048 : Wt1 A-frags (bf16x2, sigma-perm)
#define S_WS1F  8192        // 2048 : Ws1 A-frags (bf16x2, sigma-perm)
#define S_XS    10240       // 11520: bf16x2 tile, 32 pair-rows x XR
#define S_ES    21760       // 640  : edge scalars, double-buffered (2 x 320)
#define S_SPART 22400       // 1408 : 4 htiles x 352 (indexed by column)
#define S_EFAP  23808       // 576  : 16 edges x PS, bf16x2 sigma-pairs
#define S_SS2   24384       // 64   : 4 htiles x 16 edges
#define S_TOTAL 24448       // words -> 97792 B per CTA
// ---------------------------------------------------------------------------
extern __shared__ float smem[];

__global__ void __launch_bounds__(NTHREADS, 2) k_edge(
    const float* __restrict__ ew,   const float* __restrict__ b1,
    const float* __restrict__ w2,   const float* __restrict__ b2,
    const float* __restrict__ Wt1,  const float* __restrict__ bt1,
    const float* __restrict__ Wt2,  const float* __restrict__ bt2,
    const float* __restrict__ Ws1,  const float* __restrict__ bs1,
    const float* __restrict__ Ws2,  const float* __restrict__ bs2)
{
    uint32_t* w2f   = (uint32_t*)(smem + S_W2F);
    uint32_t* wt1f  = (uint32_t*)(smem + S_WT1F);
    uint32_t* ws1f  = (uint32_t*)(smem + S_WS1F);
    uint32_t* xsu   = (uint32_t*)(smem + S_XS);
    float* e_s   = smem + S_ES;
    float* spart = smem + S_SPART;
    uint32_t* efa_p = (uint32_t*)(smem + S_EFAP);
    float* ss2   = smem + S_SS2;

    const int tid  = threadIdx.x;
    const int w    = tid >> 5;
    const int lane = tid & 31;
    const int htile = w & 3;       // 16 h-rows each
    const int nhalf = w >> 2;      // 0..1 -> windows {2nhalf, 2nhalf+1}
    const int gid  = lane >> 2;    // 0..7
    const int tig  = lane & 3;     // 0..3
    const int barid = 1 + nhalf;   // named barrier per half

    // ---- one-time init: conv2 bf16 A-frags ----------------------------------
    for (int f = tid; f < 4 * 12 * 32; f += NTHREADS) {
        int ht = f / 384, rem = f % 384, kb = rem / 32, ln = rem % 32;
        int r = ht * 16 + (ln >> 2);
        int k0 = (ln & 3) * 2;
        int kk = kb >> 2, ibase = (kb & 3) * 16;
        #pragma unroll
        for (int j = 0; j < 4; ++j) {
            int h  = r + (j & 1) * 8;
            int kl = k0 + (j >> 1) * 8;
            float v0 = w2[(h * 64 + ibase + kl) * 3 + kk];
            float v1 = w2[(h * 64 + ibase + kl + 1) * 3 + kk];
            w2f[f * 4 + j] = pkbf2(v0, v1);
        }
    }
    // Wt1 bf16 A-frags with sigma k-permutation (pair P -> (s, s+8))
    for (int f = tid; f < 4 * 4 * 32; f += NTHREADS) {
        int ht = f / 128, rem = f % 128, kb = rem / 32, ln = rem % 32;
        int r = ht * 16 + (ln >> 2);
        int tg = ln & 3;
        #pragma unroll
        for (int j = 0; j < 4; ++j) {
            int P = kb * 8 + tg + (j >> 1) * 4;
            int hh = r + (j & 1) * 8;
            int s = (P >> 3) * 16 + (P & 7);
            wt1f[f * 4 + j] = pkbf2(Wt1[s * 64 + hh], Wt1[(s + 8) * 64 + hh]);
        }
    }
    // Ws1 bf16 A-frags, same sigma pairing
    for (int f = tid; f < 4 * 4 * 32; f += NTHREADS) {
        int ht = f / 128, rem = f % 128, kb = rem / 32, ln = rem % 32;
        int r = ht * 16 + (ln >> 2);
        int tg = ln & 3;
        #pragma unroll
        for (int j = 0; j < 4; ++j) {
            int P = kb * 8 + tg + (j >> 1) * 4;
            int hh = r + (j & 1) * 8;
            int s = (P >> 3) * 16 + (P & 7);
            ws1f[f * 4 + j] = pkbf2(Ws1[s * 64 + hh], Ws1[(s + 8) * 64 + hh]);
        }
    }
    // zero pad words of the tile (32 pair-rows x 16 edges x 2 sides)
    for (int f = tid; f < 32 * 2 * NE; f += NTHREADS) {
        int rp = f / (2 * NE), p = f % (2 * NE);
        int e = p >> 1, side = p & 1;
        xsu[rp * XR + e * ESLOT + side * 21] = 0u;
    }

    // ---- window-relative residue LUTs (window bases are 0 mod 8) ------------
    int cq[10], dc0[10], dc1[10];
    {
        int n0 = 0, n1 = 0, n2 = 0;
        for (int e4 = 0; e4 < 4; ++e4)
            for (int t = 0; t < TT; ++t) {
                int col = e4 * ESLOT + 1 + t;   // relative to window base
                int r8 = col & 7;
                if (r8 == gid)            cq[n0++] = col;
                if (r8 == 2 * tig)        dc0[n1++] = col;
                if (r8 == 2 * tig + 1)    dc1[n2++] = col;
            }
    }
    const int r0 = htile * 16 + gid;   // D rows r0, r0+8
    const float b2_0 = b2[r0],  b2_1 = b2[r0 + 8];
    const float bt1_0 = bt1[r0], bt1_1 = bt1[r0 + 8];
    const float wt2_0 = Wt2[r0], wt2_1 = Wt2[r0 + 8];
    const float bt2v = bt2[0];
    const float bs2v = bs2[0];

    // x1-stage mapping: thread -> pair-row (channels 2prow, 2prow+1), 2 edges
    const int prow = tid >> 3;         // 0..31
    const int xe = tid & 7;            // edges xe, xe+8
    const int c0 = prow * 2, c1 = c0 + 1;
    float a1k0[3], a1k1[3];
    float s0c = 0.f, s1c = 0.f;
    #pragma unroll
    for (int k = 0; k < 3; ++k) {
        a1k0[k] = g_A1[c0 * 3 + k];  a1k1[k] = g_A1[c1 * 3 + k];
        s0c += g_Bb[c0 * 3 + k];     s1c += g_Bb[c1 * 3 + k];
    }
    const float c3_0 = b1[c0] + s0c;
    const float c3_1 = b1[c1] + s1c;
    const float ca_0 = c3_0 - g_Bb[c0 * 3 + 0];   // t = 0
    const float ca_1 = c3_1 - g_Bb[c1 * 3 + 0];
    const float cb_0 = c3_0 - g_Bb[c0 * 3 + 2];   // t = 19
    const float cb_1 = c3_1 - g_Bb[c1 * 3 + 2];

    // efa-stage lane constants (lane == pair-row)
    const int fh0 = (lane >> 3) * 16 + (lane & 7);
    const int fh1 = fh0 + 8;

    // prefetch first group's edge scalars (320 values, 256 threads)
    float ep0 = 0.f, ep1 = 0.f;
    if (blockIdx.x < NGROUPS) {
        ep0 = ew[blockIdx.x * (NE * TT) + tid];
        if (tid < 64) ep1 = ew[blockIdx.x * (NE * TT) + 256 + tid];
    }
    e_s[tid] = ep0;
    if (tid < 64) e_s[256 + tid] = ep1;
    __syncthreads();

    int pbuf = 0;
    for (int g = blockIdx.x; g < NGROUPS; g += gridDim.x) {
        const int m0 = g * NE;

        // issue next group's prefetch early (hide DRAM latency)
        const int gn = g + gridDim.x;
        if (gn < NGROUPS) {
            ep0 = ew[gn * (NE * TT) + tid];
            if (tid < 64) ep1 = ew[gn * (NE * TT) + 256 + tid];
        }

        // ---- S1: x1 = relu(folded conv1), 2 edges per thread ------------------
        {
            const float* ebase = e_s + pbuf * 320;
            #pragma unroll
            for (int ee = 0; ee < 2; ++ee) {
                const int e = xe + ee * 8;
                const float* ep = ebase + e * TT;
                uint32_t* oa = xsu + prow * XR + e * ESLOT + 1;
                #pragma unroll
                for (int t = 0; t < TT; ++t) {
                    float x0, x1v;
                    if (t == 0) {
                        x0 = ca_0 + a1k0[1] * ep[0] + a1k0[2] * ep[1];
                        x1v = ca_1 + a1k1[1] * ep[0] + a1k1[2] * ep[1];
                    } else if (t == 19) {
                        x0 = cb_0 + a1k0[0] * ep[18] + a1k0[1] * ep[19];
                        x1v = cb_1 + a1k1[0] * ep[18] + a1k1[1] * ep[19];
                    } else {
                        x0 = c3_0 + a1k0[0]*ep[t-1] + a1k0[1]*ep[t] + a1k0[2]*ep[t+1];
                        x1v = c3_1 + a1k1[0]*ep[t-1] + a1k1[1]*ep[t] + a1k1[2]*ep[t+1];
                    }
                    oa[t] = pkbf2(fmaxf(x0, 0.f), fmaxf(x1v, 0.f));
                }
            }
        }
        __syncthreads();   // B1: full x1 tile ready

        // ---- S2/S3: conv2 + epilogue per window (named half-barriers) ---------
        #pragma unroll 1
        for (int wi = 0; wi < 2; ++wi) {
            const int wb = (nhalf * 2 + wi) * 88;   // window base column
            float d[10][4];
            #pragma unroll
            for (int q = 0; q < 10; ++q)
                #pragma unroll
                for (int j = 0; j < 4; ++j) d[q][j] = 0.f;

            #pragma unroll 1
            for (int kb = 0; kb < 12; ++kb) {
                const int fo = ((htile * 12 + kb) * 32 + lane) * 4;
                const uint4 A = *(const uint4*)(w2f + fo);
                const int rp = (kb & 3) * 8 + tig;
                const int koff = (kb >> 2) - 1;
                const uint32_t* bp = xsu + rp * XR + wb + koff;
                #pragma unroll
                for (int q = 0; q < 10; ++q) {
                    uint32_t b0 = bp[cq[q]];
                    uint32_t b1 = bp[cq[q] + 4 * XR];
                    mma_bf16(d[q], A, b0, b1);
                }
            }
            HALF_BAR(barid);   // half's conv2(win wi) reads done

            // epilogue: x2 = relu(d+b2) packed (r0, r0+8) -> pair-row
            uint32_t* op = xsu + (htile * 8 + gid) * XR + wb;
            #pragma unroll
            for (int q = 0; q < 10; ++q) {
                op[dc0[q]] = pkbf2(fmaxf(d[q][0] + b2_0, 0.f),
                                   fmaxf(d[q][2] + b2_1, 0.f));
                op[dc1[q]] = pkbf2(fmaxf(d[q][1] + b2_0, 0.f),
                                   fmaxf(d[q][3] + b2_1, 0.f));
            }
        }
        HALF_BAR(barid);   // half's x2 complete (both windows)

        // ---- S4: Wt1 MMA + score partials per window ---------------------------
        #pragma unroll 1
        for (int wi = 0; wi < 2; ++wi) {
            const int wb = (nhalf * 2 + wi) * 88;
            float d2[10][4];
            #pragma unroll
            for (int q = 0; q < 10; ++q)
                #pragma unroll
                for (int j = 0; j < 4; ++j) d2[q][j] = 0.f;

            #pragma unroll 1
            for (int kb = 0; kb < 4; ++kb) {
                const int fo = ((htile * 4 + kb) * 32 + lane) * 4;
                const uint4 A = *(const uint4*)(wt1f + fo);
                const uint32_t* bp = xsu + (kb * 8 + tig) * XR + wb;
                #pragma unroll
                for (int q = 0; q < 10; ++q) {
                    uint32_t b0 = bp[cq[q]];
                    uint32_t b1 = bp[cq[q] + 4 * XR];
                    mma_bf16(d2[q], A, b0, b1);
                }
            }
            #pragma unroll
            for (int q = 0; q < 10; ++q) {
                float s0 = tanha(d2[q][0] + bt1_0) * wt2_0
                         + tanha(d2[q][2] + bt1_1) * wt2_1;
                float s1 = tanha(d2[q][1] + bt1_0) * wt2_0
                         + tanha(d2[q][3] + bt1_1) * wt2_1;
                #pragma unroll
                for (int off = 4; off < 32; off <<= 1) {
                    s0 += __shfl_xor_sync(0xffffffffu, s0, off);
                    s1 += __shfl_xor_sync(0xffffffffu, s1, off);
                }
                if (lane < 4) {
                    spart[htile * 352 + wb + dc0[q]] = s0;
                    spart[htile * 352 + wb + dc1[q]] = s1;
                }
            }
        }
        __syncthreads();   // B4: spart + full x2 visible CTA-wide

        // ---- S5: softmax (register att) + efa + e_s prefetch store -------------
        {
            // warp w handles edges w and w+8
            float att[2];
            #pragma unroll
            for (int ee = 0; ee < 2; ++ee) {
                const int e = w + ee * 8;
                float v = -1e30f;
                if (lane < TT) {
                    int col = e * ESLOT + 1 + lane;
                    v = spart[col] + spart[352 + col] + spart[704 + col]
                      + spart[1056 + col] + bt2v;
                }
                float mx = v;
                #pragma unroll
                for (int off = 16; off; off >>= 1)
                    mx = fmaxf(mx, __shfl_xor_sync(0xffffffffu, mx, off));
                float ev = (lane < TT) ? expf(v - mx) : 0.f;
                float sum = ev;
                #pragma unroll
                for (int off = 16; off; off >>= 1)
                    sum += __shfl_xor_sync(0xffffffffu, sum, off);
                att[ee] = ev / sum;
            }
            // efa: lane = pair-row; att broadcast via shuffle
            #pragma unroll
            for (int ee = 0; ee < 2; ++ee) {
                const int e = w + ee * 8;
                const uint32_t* xr = xsu + lane * XR + e * ESLOT + 1;
                float a0 = 0.f, a1 = 0.f;
                #pragma unroll
                for (int t = 0; t < TT; ++t) {
                    uint32_t wd = xr[t];
                    float av = __shfl_sync(0xffffffffu, att[ee], t);
                    a0 += bfu_lo(wd) * av;
                    a1 += bfu_hi(wd) * av;
                }
                efa_p[e * PS + lane] = pkbf2(a0, a1);
                g_efa[(m0 + e) * 64 + fh0] = a0;
                g_efa[(m0 + e) * 64 + fh1] = a1;
            }
            // stash next group's edge scalars into the other buffer
            float* en = e_s + (1 - pbuf) * 320;
            en[tid] = ep0;
            if (tid < 64) en[256 + tid] = ep1;
        }
        __syncthreads();   // B5: efa_p + e_s(next) ready

        // ---- S6: spatial score via bf16 MMA: D[64h x 16e], K = 64 --------------
        {
            const int ht2 = w & 3;
            const int nt = w >> 2;       // 8 edges each
            float d3[4] = {0.f, 0.f, 0.f, 0.f};
            #pragma unroll
            for (int kb = 0; kb < 4; ++kb) {
                const int fo = ((ht2 * 4 + kb) * 32 + lane) * 4;
                const uint4 A = *(const uint4*)(ws1f + fo);
                uint32_t b0 = efa_p[(nt * 8 + gid) * PS + kb * 8 + tig];
                uint32_t b1 = efa_p[(nt * 8 + gid) * PS + kb * 8 + tig + 4];
                mma_bf16(d3, A, b0, b1);
            }
            const int rr0 = ht2 * 16 + gid;
            float v0 = tanha(d3[0] + bs1[rr0]) * Ws2[rr0]
                     + tanha(d3[2] + bs1[rr0 + 8]) * Ws2[rr0 + 8];
            float v1 = tanha(d3[1] + bs1[rr0]) * Ws2[rr0]
                     + tanha(d3[3] + bs1[rr0 + 8]) * Ws2[rr0 + 8];
            #pragma unroll
            for (int off = 4; off < 32; off <<= 1) {
                v0 += __shfl_xor_sync(0xffffffffu, v0, off);
                v1 += __shfl_xor_sync(0xffffffffu, v1, off);
            }
            if (lane < 4) {
                int e0 = nt * 8 + lane * 2;
                ss2[ht2 * 16 + e0]     = v0;
                ss2[ht2 * 16 + e0 + 1] = v1;
            }
        }
        __syncthreads();   // B6: ss2 ready; also protects tile for next x1

        if (tid < NE)
            g_score[m0 + tid] = ss2[tid] + ss2[16 + tid] + ss2[32 + tid]
                              + ss2[48 + tid] + bs2v;
        pbuf ^= 1;
    }
}

// ---------------------------------------------------------------------------
// K3: per-batch spatial softmax over N*N = 10000 scores
// ---------------------------------------------------------------------------
__global__ void __launch_bounds__(1024) k_spatial() {
    __shared__ float red[1024];
    __shared__ float mx_s, z_s;
    int b = blockIdx.x, tid = threadIdx.x;
    const float* sc = g_score + b * (NN * NN);

    float mx = -1e30f;
    for (int i = tid; i < NN * NN; i += 1024) mx = fmaxf(mx, sc[i]);
    red[tid] = mx;
    __syncthreads();
    for (int s = 512; s; s >>= 1) {
        if (tid < s) red[tid] = fmaxf(red[tid], red[tid + s]);
        __syncthreads();
    }
    if (tid == 0) mx_s = red[0];
    __syncthreads();
    float m = mx_s, z = 0.f;
    for (int i = tid; i < NN * NN; i += 1024) z += expf(sc[i] - m);
    red[tid] = z;
    __syncthreads();
    for (int s = 512; s; s >>= 1) {
        if (tid < s) red[tid] += red[tid + s];
        __syncthreads();
    }
    if (tid == 0) z_s = red[0];
    __syncthreads();
    float inv = 1.f / z_s;
    for (int i = tid; i < NN * NN; i += 1024)
        g_attw[b * (NN * NN) + i] = expf(sc[i] - m) * inv;
}

// ---------------------------------------------------------------------------
// K4: node aggregation + 3-layer MLP. One block per (b,i) node.
// ---------------------------------------------------------------------------
__global__ void __launch_bounds__(256) k_node(
    const float* __restrict__ Wg1, const float* __restrict__ bg1,
    const float* __restrict__ Wg2, const float* __restrict__ bg2,
    const float* __restrict__ Wout, const float* __restrict__ bout,
    float* __restrict__ out)
{
    __shared__ float nsm[256], g1s[64], g2s[64];
    const int bi = blockIdx.x;
    const int tid = threadIdx.x;
    const int h = tid & 63, quarter = tid >> 6;

    const float* efa = g_efa + (size_t)bi * NN * HH;
    const float* aw  = g_attw + bi * NN;
    float a = 0.f;
    #pragma unroll 5
    for (int j = quarter * 25; j < quarter * 25 + 25; ++j)
        a += efa[j * 64 + h] * aw[j];
    nsm[tid] = a;
    __syncthreads();
    if (tid < 64) {
        float s = nsm[tid] + nsm[tid + 64] + nsm[tid + 128] + nsm[tid + 192];
        nsm[tid] = s;
    }
    __syncthreads();
    if (tid < 64) {
        float acc = bg1[tid];
        for (int i = 0; i < 64; ++i) acc += nsm[i] * Wg1[i * 64 + tid];
        g1s[tid] = fmaxf(acc, 0.f);
    }
    __syncthreads();
    if (tid < 64) {
        float acc = bg2[tid];
        for (int i = 0; i < 64; ++i) acc += g1s[i] * Wg2[i * 64 + tid];
        g2s[tid] = fmaxf(acc, 0.f);
    }
    __syncthreads();
    if (tid < OO) {
        float acc = bout[tid];
        for (int i = 0; i < 64; ++i) acc += g2s[i] * Wout[i * OO + tid];
        out[bi * OO + tid] = fmaxf(acc, 0.f);
    }
}

// ---------------------------------------------------------------------------
extern "C" void kernel_launch(void* const* d_in, const int* in_sizes, int n_in,
                              void* d_out, int out_size) {
    const float* ew   = (const float*)d_in[0];
    const float* We   = (const float*)d_in[1];
    const float* be   = (const float*)d_in[2];
    const float* w1   = (const float*)d_in[3];
    const float* b1   = (const float*)d_in[4];
    const float* w2   = (const float*)d_in[5];
    const float* b2   = (const float*)d_in[6];
    const float* Wt1  = (const float*)d_in[7];
    const float* bt1  = (const float*)d_in[8];
    const float* Wt2  = (const float*)d_in[9];
    const float* bt2  = (const float*)d_in[10];
    const float* Ws1  = (const float*)d_in[11];
    const float* bs1  = (const float*)d_in[12];
    const float* Ws2  = (const float*)d_in[13];
    const float* bs2  = (const float*)d_in[14];
    const float* Wg1  = (const float*)d_in[15];
    const float* bg1  = (const float*)d_in[16];
    const float* Wg2  = (const float*)d_in[17];
    const float* bg2  = (const float*)d_in[18];
    const float* Wout = (const float*)d_in[19];
    const float* bout = (const float*)d_in[20];
    float* out = (float*)d_out;

    const int smem_bytes = S_TOTAL * 4;  // 97792 B per CTA
    cudaFuncSetAttribute(k_edge, cudaFuncAttributeMaxDynamicSharedMemorySize,
                         smem_bytes);

    k_prep<<<1, 256>>>(w1, We, be);
    k_edge<<<NBLOCKS, NTHREADS, smem_bytes>>>(ew, b1, w2, b2, Wt1, bt1,
                                              Wt2, bt2, Ws1, bs1, Ws2, bs2);
    k_spatial<<<BB, 1024>>>();
    k_node<<<BB * NN, 256>>>(Wg1, bg1, Wg2, bg2, Wout, bout, out);
}

// round 13
// speedup vs baseline: 1.0733x; 1.0733x over previous
#include <cuda_runtime.h>
#include <cuda_bf16.h>
#include <math.h>
#include <stdint.h>

// Problem constants
#define BB 4
#define NN 100
#define TT 20
#define HH 64
#define OO 128
#define MM 40000            // B*N*N edges
#define NE 8                // edges per group
#define NGROUPS (MM/NE)     // 5000
#define ESLOT 22            // [0]=left pad, [1..20]=t, [21]=right pad
#define XR 200              // row stride (=8 mod 32 for conflict-free MMA gathers)
#define NTHREADS 256
#define NBLOCKS 296         // 2 CTAs per SM

// Scratch
__device__ float g_efa[MM * HH];   // 10.24 MB
__device__ float g_score[MM];
__device__ float g_attw[MM];

// ---- helpers ---------------------------------------------------------------
__device__ __forceinline__ float tanha(float x) {
    float y;
    asm("tanh.approx.f32 %0, %1;" : "=f"(y) : "f"(x));
    return y;
}
__device__ __forceinline__ uint32_t f2tf32(float x) {
    uint32_t r;
    asm("cvt.rna.tf32.f32 %0, %1;" : "=r"(r) : "f"(x));
    return r;
}
// pack two f32 -> bf16x2 word; 'lo' lands in low 16 bits (first element)
__device__ __forceinline__ uint32_t pkbf2(float lo, float hi) {
    uint32_t r;
    asm("cvt.rn.bf16x2.f32 %0, %1, %2;" : "=r"(r) : "f"(hi), "f"(lo));
    return r;
}
__device__ __forceinline__ float bfu_lo(uint32_t w) {
    return __uint_as_float(w << 16);
}
__device__ __forceinline__ float bfu_hi(uint32_t w) {
    return __uint_as_float(w & 0xffff0000u);
}
__device__ __forceinline__ void mma_bf16(float d[4], uint4 a,
                                         uint32_t b0, uint32_t b1) {
    asm volatile(
        "mma.sync.aligned.m16n8k16.row.col.f32.bf16.bf16.f32 "
        "{%0,%1,%2,%3},{%4,%5,%6,%7},{%8,%9},{%0,%1,%2,%3};"
        : "+f"(d[0]), "+f"(d[1]), "+f"(d[2]), "+f"(d[3])
        : "r"(a.x), "r"(a.y), "r"(a.z), "r"(a.w), "r"(b0), "r"(b1));
}
__device__ __forceinline__ void mma_tf32(float d[4], uint4 a,
                                         uint32_t b0, uint32_t b1) {
    asm volatile(
        "mma.sync.aligned.m16n8k8.row.col.f32.tf32.tf32.f32 "
        "{%0,%1,%2,%3},{%4,%5,%6,%7},{%8,%9},{%0,%1,%2,%3};"
        : "+f"(d[0]), "+f"(d[1]), "+f"(d[2]), "+f"(d[3])
        : "r"(a.x), "r"(a.y), "r"(a.z), "r"(a.w), "r"(b0), "r"(b1));
}

// ---------------------------------------------------------------------------
// K2: fused per-edge pipeline (R8 config: 256 threads, 8 edges/group,
// 2 CTAs/SM, scalar conflict-free gathers). conv1-fold computed in-kernel.
// SMEM word offsets:
#define S_W2F   0           // 6144 : conv2 A-frags (bf16x2)
#define S_WT1F  6144        // 2048 : Wt1 A-frags (bf16x2, sigma-perm)
#define S_WS1F  8192        // 4096 : Ws1 A-frags (tf32)
#define S_XS    12288       // 6400 : bf16x2 tile, 32 pair-rows x XR
#define S_ES    18688       // 160
#define S_ATT   18848       // 160
#define S_SPART 19008       // 704  : 4 htiles x 176 (indexed by column)
#define S_EFA   19712       // 544  : 8 edges x 68 (padded stride)
#define S_SS2   20256       // 32
#define S_A1    20288       // 192  : folded conv1 A
#define S_BB    20480       // 192  : folded conv1 B
#define S_TOTAL 20672       // words -> 82688 B per CTA
// ---------------------------------------------------------------------------
extern __shared__ float smem[];

__global__ void __launch_bounds__(NTHREADS, 2) k_edge(
    const float* __restrict__ ew,   const float* __restrict__ We,
    const float* __restrict__ be,   const float* __restrict__ w1,
    const float* __restrict__ b1,
    const float* __restrict__ w2,   const float* __restrict__ b2,
    const float* __restrict__ Wt1,  const float* __restrict__ bt1,
    const float* __restrict__ Wt2,  const float* __restrict__ bt2,
    const float* __restrict__ Ws1,  const float* __restrict__ bs1,
    const float* __restrict__ Ws2,  const float* __restrict__ bs2)
{
    uint32_t* w2f   = (uint32_t*)(smem + S_W2F);
    uint32_t* wt1f  = (uint32_t*)(smem + S_WT1F);
    float* ws1f  = smem + S_WS1F;
    uint32_t* xsu   = (uint32_t*)(smem + S_XS);
    float* e_s   = smem + S_ES;
    float* att_s = smem + S_ATT;
    float* spart = smem + S_SPART;
    float* efa_s = smem + S_EFA;
    float* ss2   = smem + S_SS2;
    float* a1s   = smem + S_A1;
    float* bbs   = smem + S_BB;

    const int tid  = threadIdx.x;
    const int w    = tid >> 5;
    const int lane = tid & 31;
    const int htile = w & 3;       // 16 h-rows each
    const int nhalf = w >> 2;      // 0..1, one 4-edge window (80 cols)
    const int gid  = lane >> 2;    // 0..7
    const int tig  = lane & 3;     // 0..3

    // ---- one-time init: folded conv1 (same summation order as before) -------
    if (tid < HH * 3) {
        int h = tid / 3, k = tid % 3;
        float a = 0.f, c = 0.f;
        for (int i = 0; i < HH; ++i) {
            float wv = w1[(h * HH + i) * 3 + k];
            a += wv * We[i];
            c += wv * be[i];
        }
        a1s[tid] = a;
        bbs[tid] = c;
    }
    // ---- one-time init: conv2 bf16 A-frags ----------------------------------
    for (int f = tid; f < 4 * 12 * 32; f += NTHREADS) {
        int ht = f / 384, rem = f % 384, kb = rem / 32, ln = rem % 32;
        int r = ht * 16 + (ln >> 2);
        int k0 = (ln & 3) * 2;
        int kk = kb >> 2, ibase = (kb & 3) * 16;
        #pragma unroll
        for (int j = 0; j < 4; ++j) {
            int h  = r + (j & 1) * 8;
            int kl = k0 + (j >> 1) * 8;
            float v0 = w2[(h * 64 + ibase + kl) * 3 + kk];
            float v1 = w2[(h * 64 + ibase + kl + 1) * 3 + kk];
            w2f[f * 4 + j] = pkbf2(v0, v1);
        }
    }
    // Wt1 bf16 A-frags with sigma k-permutation (pair P -> (s, s+8))
    for (int f = tid; f < 4 * 4 * 32; f += NTHREADS) {
        int ht = f / 128, rem = f % 128, kb = rem / 32, ln = rem % 32;
        int r = ht * 16 + (ln >> 2);
        int tg = ln & 3;
        #pragma unroll
        for (int j = 0; j < 4; ++j) {
            int P = kb * 8 + tg + (j >> 1) * 4;
            int hh = r + (j & 1) * 8;
            int s = (P >> 3) * 16 + (P & 7);
            wt1f[f * 4 + j] = pkbf2(Wt1[s * 64 + hh], Wt1[(s + 8) * 64 + hh]);
        }
    }
    // Ws1 tf32 A-frags
    for (int f = tid; f < 4 * 8 * 32; f += NTHREADS) {
        int ht = f / 256, rem = f % 256, kb = rem / 32, ln = rem % 32;
        int base_r = ht * 16 + (ln >> 2);
        int base_c = kb * 8 + (ln & 3);
        #pragma unroll
        for (int j = 0; j < 4; ++j) {
            int h = base_r + (j & 1) * 8;
            int i = base_c + (j >> 1) * 4;
            ws1f[f * 4 + j] = __uint_as_float(f2tf32(Ws1[i * 64 + h]));
        }
    }
    // zero pad words of the tile (32 pair-rows)
    for (int f = tid; f < 32 * 2 * NE; f += NTHREADS) {
        int rp = f / (2 * NE), p = f % (2 * NE);
        int e = p >> 1, side = p & 1;
        xsu[rp * XR + e * ESLOT + side * 21] = 0u;
    }
    __syncthreads();   // a1s/bbs (and frags) ready for per-thread constants

    // ---- residue-perm column LUTs (conflict-free MMA gathers) ---------------
    int cq[10], dc0[10], dc1[10];
    {
        const int wb = nhalf * 4 * ESLOT;
        int n0 = 0, n1 = 0, n2 = 0;
        for (int e4 = 0; e4 < 4; ++e4)
            for (int t = 0; t < TT; ++t) {
                int col = wb + e4 * ESLOT + 1 + t;
                int r8 = col & 7;
                if (r8 == gid)            cq[n0++] = col;
                if (r8 == 2 * tig)        dc0[n1++] = col;
                if (r8 == 2 * tig + 1)    dc1[n2++] = col;
            }
    }
    const int r0 = htile * 16 + gid;   // D rows r0, r0+8
    const float b2_0 = b2[r0],  b2_1 = b2[r0 + 8];
    const float bt1_0 = bt1[r0], bt1_1 = bt1[r0 + 8];
    const float wt2_0 = Wt2[r0], wt2_1 = Wt2[r0 + 8];
    const float bt2v = bt2[0];
    const float bs2v = bs2[0];

    // x1-stage mapping: thread -> pair-row (channels 2prow, 2prow+1), one edge
    const int prow = tid >> 3;         // 0..31
    const int xe = tid & 7;            // edge 0..7
    const int c0 = prow * 2, c1 = c0 + 1;
    float a1k0[3], a1k1[3];
    float s0c = 0.f, s1c = 0.f;
    #pragma unroll
    for (int k = 0; k < 3; ++k) {
        a1k0[k] = a1s[c0 * 3 + k];  a1k1[k] = a1s[c1 * 3 + k];
        s0c += bbs[c0 * 3 + k];     s1c += bbs[c1 * 3 + k];
    }
    const float c3_0 = b1[c0] + s0c;
    const float c3_1 = b1[c1] + s1c;
    const float ca_0 = c3_0 - bbs[c0 * 3 + 0];   // t = 0
    const float ca_1 = c3_1 - bbs[c1 * 3 + 0];
    const float cb_0 = c3_0 - bbs[c0 * 3 + 2];   // t = 19
    const float cb_1 = c3_1 - bbs[c1 * 3 + 2];

    // efa-stage mapping: warp covers 8 pair-rows x 4 edges
    const int fpr = (w & 3) * 8 + (lane & 7);     // pair-row 0..31
    const int fe  = (w >> 2) * 4 + (lane >> 3);   // edge 0..7
    const int fh0 = (fpr >> 3) * 16 + (fpr & 7);
    const int fh1 = fh0 + 8;

    // prefetch first group's edge scalars
    float epref = 0.f;
    if (blockIdx.x < NGROUPS && tid < NE * TT)
        epref = ew[blockIdx.x * (NE * TT) + tid];

    for (int g = blockIdx.x; g < NGROUPS; g += gridDim.x) {
        const int m0 = g * NE;

        if (tid < NE * TT) e_s[tid] = epref;
        const int gn = g + gridDim.x;
        if (gn < NGROUPS && tid < NE * TT)
            epref = ew[gn * (NE * TT) + tid];
        __syncthreads();

        // ---- x1 = relu(folded conv1), packed bf16x2 by channel pair ----------
        {
            const float* ep = e_s + xe * TT;
            uint32_t* oa = xsu + prow * XR + xe * ESLOT + 1;
            #pragma unroll
            for (int t = 0; t < TT; ++t) {
                float x0, x1v;
                if (t == 0) {
                    x0 = ca_0 + a1k0[1] * ep[0] + a1k0[2] * ep[1];
                    x1v = ca_1 + a1k1[1] * ep[0] + a1k1[2] * ep[1];
                } else if (t == 19) {
                    x0 = cb_0 + a1k0[0] * ep[18] + a1k0[1] * ep[19];
                    x1v = cb_1 + a1k1[0] * ep[18] + a1k1[1] * ep[19];
                } else {
                    x0 = c3_0 + a1k0[0]*ep[t-1] + a1k0[1]*ep[t] + a1k0[2]*ep[t+1];
                    x1v = c3_1 + a1k1[0]*ep[t-1] + a1k1[1]*ep[t] + a1k1[2]*ep[t+1];
                }
                oa[t] = pkbf2(fmaxf(x0, 0.f), fmaxf(x1v, 0.f));
            }
        }
        __syncthreads();

        // ---- conv2 via bf16 MMA: D[64 x 160], K = 192 (conflict-free B) ------
        float d[10][4];
        #pragma unroll
        for (int q = 0; q < 10; ++q)
            #pragma unroll
            for (int j = 0; j < 4; ++j) d[q][j] = 0.f;

        #pragma unroll 2
        for (int kb = 0; kb < 12; ++kb) {
            const int fo = ((htile * 12 + kb) * 32 + lane) * 4;
            const uint4 A = *(const uint4*)(w2f + fo);
            const int rp = (kb & 3) * 8 + tig;
            const int koff = (kb >> 2) - 1;
            const uint32_t* bp = xsu + rp * XR + koff;
            #pragma unroll
            for (int q = 0; q < 10; ++q) {
                uint32_t b0 = bp[cq[q]];
                uint32_t b1 = bp[cq[q] + 4 * XR];
                mma_bf16(d[q], A, b0, b1);
            }
        }
        __syncthreads();  // all B reads done before overwriting the tile

        // ---- epilogue: x2 = relu(d+b2) packed (r0, r0+8) -> pair-row ----------
        {
            uint32_t* op = xsu + (htile * 8 + gid) * XR;
            #pragma unroll
            for (int q = 0; q < 10; ++q) {
                op[dc0[q]] = pkbf2(fmaxf(d[q][0] + b2_0, 0.f),
                                   fmaxf(d[q][2] + b2_1, 0.f));
                op[dc1[q]] = pkbf2(fmaxf(d[q][1] + b2_0, 0.f),
                                   fmaxf(d[q][3] + b2_1, 0.f));
            }
        }
        __syncthreads();

        // ---- u_pre = Wt1^T @ x2 via bf16 MMA on packed tile -------------------
        float d2[10][4];
        #pragma unroll
        for (int q = 0; q < 10; ++q)
            #pragma unroll
            for (int j = 0; j < 4; ++j) d2[q][j] = 0.f;

        #pragma unroll
        for (int kb = 0; kb < 4; ++kb) {
            const int fo = ((htile * 4 + kb) * 32 + lane) * 4;
            const uint4 A = *(const uint4*)(wt1f + fo);
            const uint32_t* bp = xsu + (kb * 8 + tig) * XR;
            #pragma unroll
            for (int q = 0; q < 10; ++q) {
                uint32_t b0 = bp[cq[q]];
                uint32_t b1 = bp[cq[q] + 4 * XR];
                mma_bf16(d2[q], A, b0, b1);
            }
        }

        // ---- score partials (indexed by column) -------------------------------
        #pragma unroll
        for (int q = 0; q < 10; ++q) {
            float s0 = tanha(d2[q][0] + bt1_0) * wt2_0
                     + tanha(d2[q][2] + bt1_1) * wt2_1;
            float s1 = tanha(d2[q][1] + bt1_0) * wt2_0
                     + tanha(d2[q][3] + bt1_1) * wt2_1;
            #pragma unroll
            for (int off = 4; off < 32; off <<= 1) {
                s0 += __shfl_xor_sync(0xffffffffu, s0, off);
                s1 += __shfl_xor_sync(0xffffffffu, s1, off);
            }
            if (lane < 4) {
                spart[htile * 176 + dc0[q]] = s0;
                spart[htile * 176 + dc1[q]] = s1;
            }
        }
        __syncthreads();

        // ---- temporal softmax: warp w handles edge w --------------------------
        {
            float v = -1e30f;
            if (lane < TT) {
                int col = w * ESLOT + 1 + lane;
                v = spart[col] + spart[176 + col] + spart[352 + col]
                  + spart[528 + col] + bt2v;
            }
            float mx = v;
            #pragma unroll
            for (int off = 16; off; off >>= 1)
                mx = fmaxf(mx, __shfl_xor_sync(0xffffffffu, mx, off));
            float ev = (lane < TT) ? expf(v - mx) : 0.f;
            float sum = ev;
            #pragma unroll
            for (int off = 16; off; off >>= 1)
                sum += __shfl_xor_sync(0xffffffffu, sum, off);
            if (lane < TT) att_s[w * TT + lane] = ev / sum;
        }
        __syncthreads();

        // ---- efa: (pair-row, edge) per thread; unpack bf16x2 ------------------
        {
            const uint32_t* xr = xsu + fpr * XR + fe * ESLOT + 1;
            const float* at = att_s + fe * TT;
            float a0 = 0.f, a1 = 0.f;
            #pragma unroll
            for (int t = 0; t < TT; ++t) {
                uint32_t wd = xr[t];
                float av = at[t];
                a0 += bfu_lo(wd) * av;
                a1 += bfu_hi(wd) * av;
            }
            efa_s[fe * 68 + fh0] = a0;
            efa_s[fe * 68 + fh1] = a1;
            g_efa[(m0 + fe) * 64 + fh0] = a0;
            g_efa[(m0 + fe) * 64 + fh1] = a1;
        }
        __syncthreads();

        // ---- spatial score via tf32 MMA: D[64h x 8e], K = 64 ------------------
        if (w < 4) {
            const int ht2 = w;
            float d3[4] = {0.f, 0.f, 0.f, 0.f};
            #pragma unroll
            for (int kb = 0; kb < 8; ++kb) {
                const int fo = ((ht2 * 8 + kb) * 32 + lane) * 4;
                const uint4 A = *(const uint4*)(ws1f + fo);
                const float* bp = efa_s + gid * 68 + kb * 8 + tig;
                uint32_t b0 = __float_as_uint(bp[0]);
                uint32_t b1 = __float_as_uint(bp[4]);
                mma_tf32(d3, A, b0, b1);
            }
            const int rr0 = ht2 * 16 + gid;
            float v0 = tanha(d3[0] + bs1[rr0]) * Ws2[rr0]
                     + tanha(d3[2] + bs1[rr0 + 8]) * Ws2[rr0 + 8];
            float v1 = tanha(d3[1] + bs1[rr0]) * Ws2[rr0]
                     + tanha(d3[3] + bs1[rr0 + 8]) * Ws2[rr0 + 8];
            #pragma unroll
            for (int off = 4; off < 32; off <<= 1) {
                v0 += __shfl_xor_sync(0xffffffffu, v0, off);
                v1 += __shfl_xor_sync(0xffffffffu, v1, off);
            }
            if (lane < 4) {
                int e0 = lane * 2;
                ss2[ht2 * 8 + e0]     = v0;
                ss2[ht2 * 8 + e0 + 1] = v1;
            }
        }
        __syncthreads();
        if (tid < NE)
            g_score[m0 + tid] = ss2[tid] + ss2[8 + tid] + ss2[16 + tid]
                              + ss2[24 + tid] + bs2v;
    }
}

// ---------------------------------------------------------------------------
// K3: per-batch spatial softmax over N*N = 10000 scores
// ---------------------------------------------------------------------------
__global__ void __launch_bounds__(1024) k_spatial() {
    __shared__ float red[1024];
    __shared__ float mx_s, z_s;
    int b = blockIdx.x, tid = threadIdx.x;
    const float* sc = g_score + b * (NN * NN);

    float mx = -1e30f;
    for (int i = tid; i < NN * NN; i += 1024) mx = fmaxf(mx, sc[i]);
    red[tid] = mx;
    __syncthreads();
    for (int s = 512; s; s >>= 1) {
        if (tid < s) red[tid] = fmaxf(red[tid], red[tid + s]);
        __syncthreads();
    }
    if (tid == 0) mx_s = red[0];
    __syncthreads();
    float m = mx_s, z = 0.f;
    for (int i = tid; i < NN * NN; i += 1024) z += expf(sc[i] - m);
    red[tid] = z;
    __syncthreads();
    for (int s = 512; s; s >>= 1) {
        if (tid < s) red[tid] += red[tid + s];
        __syncthreads();
    }
    if (tid == 0) z_s = red[0];
    __syncthreads();
    float inv = 1.f / z_s;
    for (int i = tid; i < NN * NN; i += 1024)
        g_attw[b * (NN * NN) + i] = expf(sc[i] - m) * inv;
}

// ---------------------------------------------------------------------------
// K4: node aggregation + 3-layer MLP. One block per (b,i) node.
// ---------------------------------------------------------------------------
__global__ void __launch_bounds__(256) k_node(
    const float* __restrict__ Wg1, const float* __restrict__ bg1,
    const float* __restrict__ Wg2, const float* __restrict__ bg2,
    const float* __restrict__ Wout, const float* __restrict__ bout,
    float* __restrict__ out)
{
    __shared__ float nsm[256], g1s[64], g2s[64];
    const int bi = blockIdx.x;
    const int tid = threadIdx.x;
    const int h = tid & 63, quarter = tid >> 6;

    const float* efa = g_efa + (size_t)bi * NN * HH;
    const float* aw  = g_attw + bi * NN;
    float a = 0.f;
    #pragma unroll 5
    for (int j = quarter * 25; j < quarter * 25 + 25; ++j)
        a += efa[j * 64 + h] * aw[j];
    nsm[tid] = a;
    __syncthreads();
    if (tid < 64) {
        float s = nsm[tid] + nsm[tid + 64] + nsm[tid + 128] + nsm[tid + 192];
        nsm[tid] = s;
    }
    __syncthreads();
    if (tid < 64) {
        float acc = bg1[tid];
        for (int i = 0; i < 64; ++i) acc += nsm[i] * Wg1[i * 64 + tid];
        g1s[tid] = fmaxf(acc, 0.f);
    }
    __syncthreads();
    if (tid < 64) {
        float acc = bg2[tid];
        for (int i = 0; i < 64; ++i) acc += g1s[i] * Wg2[i * 64 + tid];
        g2s[tid] = fmaxf(acc, 0.f);
    }
    __syncthreads();
    if (tid < OO) {
        float acc = bout[tid];
        for (int i = 0; i < 64; ++i) acc += g2s[i] * Wout[i * OO + tid];
        out[bi * OO + tid] = fmaxf(acc, 0.f);
    }
}

// ---------------------------------------------------------------------------
extern "C" void kernel_launch(void* const* d_in, const int* in_sizes, int n_in,
                              void* d_out, int out_size) {
    const float* ew   = (const float*)d_in[0];
    const float* We   = (const float*)d_in[1];
    const float* be   = (const float*)d_in[2];
    const float* w1   = (const float*)d_in[3];
    const float* b1   = (const float*)d_in[4];
    const float* w2   = (const float*)d_in[5];
    const float* b2   = (const float*)d_in[6];
    const float* Wt1  = (const float*)d_in[7];
    const float* bt1  = (const float*)d_in[8];
    const float* Wt2  = (const float*)d_in[9];
    const float* bt2  = (const float*)d_in[10];
    const float* Ws1  = (const float*)d_in[11];
    const float* bs1  = (const float*)d_in[12];
    const float* Ws2  = (const float*)d_in[13];
    const float* bs2  = (const float*)d_in[14];
    const float* Wg1  = (const float*)d_in[15];
    const float* bg1  = (const float*)d_in[16];
    const float* Wg2  = (const float*)d_in[17];
    const float* bg2  = (const float*)d_in[18];
    const float* Wout = (const float*)d_in[19];
    const float* bout = (const float*)d_in[20];
    float* out = (float*)d_out;

    const int smem_bytes = S_TOTAL * 4;  // 82688 B per CTA
    cudaFuncSetAttribute(k_edge, cudaFuncAttributeMaxDynamicSharedMemorySize,
                         smem_bytes);

    k_edge<<<NBLOCKS, NTHREADS, smem_bytes>>>(ew, We, be, w1, b1, w2, b2,
                                              Wt1, bt1, Wt2, bt2,
                                              Ws1, bs1, Ws2, bs2);
    k_spatial<<<BB, 1024>>>();
    k_node<<<BB * NN, 256>>>(Wg1, bg1, Wg2, bg2, Wout, bout, out);
}

// round 14
// speedup vs baseline: 1.1729x; 1.0928x over previous
#include <cuda_runtime.h>
#include <cuda_bf16.h>
#include <math.h>
#include <stdint.h>

// Problem constants
#define BB 4
#define NN 100
#define TT 20
#define HH 64
#define OO 128
#define MM 40000            // B*N*N edges
#define NE 8                // edges per group
#define NGROUPS (MM/NE)     // 5000
#define ESLOT 22            // [0]=left pad, [1..20]=t, [21]=right pad
#define XR 200              // row stride (=8 mod 32 for conflict-free MMA gathers)
#define NTHREADS 256
#define NBLOCKS 296         // 2 CTAs per SM

// Scratch
__device__ float g_efa[MM * HH];   // 10.24 MB
__device__ float g_score[MM];
__device__ float g_attw[MM];

// ---- helpers ---------------------------------------------------------------
__device__ __forceinline__ float tanha(float x) {
    float y;
    asm("tanh.approx.f32 %0, %1;" : "=f"(y) : "f"(x));
    return y;
}
__device__ __forceinline__ uint32_t f2tf32(float x) {
    uint32_t r;
    asm("cvt.rna.tf32.f32 %0, %1;" : "=r"(r) : "f"(x));
    return r;
}
// pack two f32 -> bf16x2 word; 'lo' lands in low 16 bits (first element)
__device__ __forceinline__ uint32_t pkbf2(float lo, float hi) {
    uint32_t r;
    asm("cvt.rn.bf16x2.f32 %0, %1, %2;" : "=r"(r) : "f"(hi), "f"(lo));
    return r;
}
__device__ __forceinline__ float bfu_lo(uint32_t w) {
    return __uint_as_float(w << 16);
}
__device__ __forceinline__ float bfu_hi(uint32_t w) {
    return __uint_as_float(w & 0xffff0000u);
}
__device__ __forceinline__ void mma_bf16(float* d, uint4 a,
                                         uint32_t b0, uint32_t b1) {
    asm volatile(
        "mma.sync.aligned.m16n8k16.row.col.f32.bf16.bf16.f32 "
        "{%0,%1,%2,%3},{%4,%5,%6,%7},{%8,%9},{%0,%1,%2,%3};"
        : "+f"(d[0]), "+f"(d[1]), "+f"(d[2]), "+f"(d[3])
        : "r"(a.x), "r"(a.y), "r"(a.z), "r"(a.w), "r"(b0), "r"(b1));
}
__device__ __forceinline__ void mma_tf32(float* d, uint4 a,
                                         uint32_t b0, uint32_t b1) {
    asm volatile(
        "mma.sync.aligned.m16n8k8.row.col.f32.tf32.tf32.f32 "
        "{%0,%1,%2,%3},{%4,%5,%6,%7},{%8,%9},{%0,%1,%2,%3};"
        : "+f"(d[0]), "+f"(d[1]), "+f"(d[2]), "+f"(d[3])
        : "r"(a.x), "r"(a.y), "r"(a.z), "r"(a.w), "r"(b0), "r"(b1));
}

// ---------------------------------------------------------------------------
// K2: fused pipeline. GEMM warps remapped to 2 h-groups x 4 n-quarters
// (B-operand redundancy 4x -> 2x; L1-byte bound per R13 ncu).
// SMEM word offsets:
#define S_W2F   0           // 6144 : conv2 A-frags (bf16x2)
#define S_WT1F  6144        // 2048 : Wt1 A-frags (bf16x2, sigma-perm)
#define S_WS1F  8192        // 4096 : Ws1 A-frags (tf32)
#define S_XS    12288       // 6400 : bf16x2 tile, 32 pair-rows x XR
#define S_ES    18688       // 160
#define S_ATT   18848       // 160
#define S_SPART 19008       // 352  : 2 h-groups x 176 (indexed by column)
#define S_EFA   19360       // 544  : 8 edges x 68 (padded stride)
#define S_SS2   19904       // 32
#define S_A1    19936       // 192  : folded conv1 A
#define S_BB    20128       // 192  : folded conv1 B
#define S_TOTAL 20320       // words -> 81280 B per CTA
// ---------------------------------------------------------------------------
extern __shared__ float smem[];

__global__ void __launch_bounds__(NTHREADS, 2) k_edge(
    const float* __restrict__ ew,   const float* __restrict__ We,
    const float* __restrict__ be,   const float* __restrict__ w1,
    const float* __restrict__ b1,
    const float* __restrict__ w2,   const float* __restrict__ b2,
    const float* __restrict__ Wt1,  const float* __restrict__ bt1,
    const float* __restrict__ Wt2,  const float* __restrict__ bt2,
    const float* __restrict__ Ws1,  const float* __restrict__ bs1,
    const float* __restrict__ Ws2,  const float* __restrict__ bs2)
{
    uint32_t* w2f   = (uint32_t*)(smem + S_W2F);
    uint32_t* wt1f  = (uint32_t*)(smem + S_WT1F);
    float* ws1f  = smem + S_WS1F;
    uint32_t* xsu   = (uint32_t*)(smem + S_XS);
    float* e_s   = smem + S_ES;
    float* att_s = smem + S_ATT;
    float* spart = smem + S_SPART;
    float* efa_s = smem + S_EFA;
    float* ss2   = smem + S_SS2;
    float* a1s   = smem + S_A1;
    float* bbs   = smem + S_BB;

    const int tid  = threadIdx.x;
    const int w    = tid >> 5;
    const int lane = tid & 31;
    const int hgrp = w & 1;        // h-group: htiles {2hgrp, 2hgrp+1} (32 rows)
    const int nq   = w >> 1;       // n-quarter: 5 q-tiles (40 cols)
    const int gid  = lane >> 2;    // 0..7
    const int tig  = lane & 3;     // 0..3

    // ---- one-time init: folded conv1 (same summation order) ------------------
    if (tid < HH * 3) {
        int h = tid / 3, k = tid % 3;
        float a = 0.f, c = 0.f;
        for (int i = 0; i < HH; ++i) {
            float wv = w1[(h * HH + i) * 3 + k];
            a += wv * We[i];
            c += wv * be[i];
        }
        a1s[tid] = a;
        bbs[tid] = c;
    }
    // ---- one-time init: conv2 bf16 A-frags -----------------------------------
    for (int f = tid; f < 4 * 12 * 32; f += NTHREADS) {
        int ht = f / 384, rem = f % 384, kb = rem / 32, ln = rem % 32;
        int r = ht * 16 + (ln >> 2);
        int k0 = (ln & 3) * 2;
        int kk = kb >> 2, ibase = (kb & 3) * 16;
        #pragma unroll
        for (int j = 0; j < 4; ++j) {
            int h  = r + (j & 1) * 8;
            int kl = k0 + (j >> 1) * 8;
            float v0 = w2[(h * 64 + ibase + kl) * 3 + kk];
            float v1 = w2[(h * 64 + ibase + kl + 1) * 3 + kk];
            w2f[f * 4 + j] = pkbf2(v0, v1);
        }
    }
    // Wt1 bf16 A-frags with sigma k-permutation (pair P -> (s, s+8))
    for (int f = tid; f < 4 * 4 * 32; f += NTHREADS) {
        int ht = f / 128, rem = f % 128, kb = rem / 32, ln = rem % 32;
        int r = ht * 16 + (ln >> 2);
        int tg = ln & 3;
        #pragma unroll
        for (int j = 0; j < 4; ++j) {
            int P = kb * 8 + tg + (j >> 1) * 4;
            int hh = r + (j & 1) * 8;
            int s = (P >> 3) * 16 + (P & 7);
            wt1f[f * 4 + j] = pkbf2(Wt1[s * 64 + hh], Wt1[(s + 8) * 64 + hh]);
        }
    }
    // Ws1 tf32 A-frags
    for (int f = tid; f < 4 * 8 * 32; f += NTHREADS) {
        int ht = f / 256, rem = f % 256, kb = rem / 32, ln = rem % 32;
        int base_r = ht * 16 + (ln >> 2);
        int base_c = kb * 8 + (ln & 3);
        #pragma unroll
        for (int j = 0; j < 4; ++j) {
            int h = base_r + (j & 1) * 8;
            int i = base_c + (j >> 1) * 4;
            ws1f[f * 4 + j] = __uint_as_float(f2tf32(Ws1[i * 64 + h]));
        }
    }
    // zero pad words of the tile (32 pair-rows)
    for (int f = tid; f < 32 * 2 * NE; f += NTHREADS) {
        int rp = f / (2 * NE), p = f % (2 * NE);
        int e = p >> 1, side = p & 1;
        xsu[rp * XR + e * ESLOT + side * 21] = 0u;
    }
    __syncthreads();   // a1s/bbs ready for per-thread constants

    // ---- residue-perm column LUTs: warp takes q in [qb, qb+5) of its window --
    int cq[5], dc0[5], dc1[5];
    {
        const int wb = (nq >> 1) * 4 * ESLOT;   // window base (0 or 88)
        const int qb = (nq & 1) * 5;
        int n0 = 0, n1 = 0, n2 = 0;
        for (int e4 = 0; e4 < 4; ++e4)
            for (int t = 0; t < TT; ++t) {
                int col = wb + e4 * ESLOT + 1 + t;
                int r8 = col & 7;
                if (r8 == gid)         { if (n0 >= qb && n0 < qb + 5) cq[n0 - qb] = col;  n0++; }
                if (r8 == 2 * tig)     { if (n1 >= qb && n1 < qb + 5) dc0[n1 - qb] = col; n1++; }
                if (r8 == 2 * tig + 1) { if (n2 >= qb && n2 < qb + 5) dc1[n2 - qb] = col; n2++; }
            }
    }
    const int ht0 = 2 * hgrp, ht1 = 2 * hgrp + 1;
    const int ra = ht0 * 16 + gid;     // D rows ra, ra+8 (htile0), ra+16, ra+24 (htile1)
    const float b2v0 = b2[ra],      b2v1 = b2[ra + 8];
    const float b2v2 = b2[ra + 16], b2v3 = b2[ra + 24];
    const float bt1v0 = bt1[ra],      bt1v1 = bt1[ra + 8];
    const float bt1v2 = bt1[ra + 16], bt1v3 = bt1[ra + 24];
    const float wt2v0 = Wt2[ra],      wt2v1 = Wt2[ra + 8];
    const float wt2v2 = Wt2[ra + 16], wt2v3 = Wt2[ra + 24];
    const float bt2v = bt2[0];
    const float bs2v = bs2[0];

    // x1-stage mapping: thread -> pair-row (channels 2prow, 2prow+1), one edge
    const int prow = tid >> 3;         // 0..31
    const int xe = tid & 7;            // edge 0..7
    const int c0 = prow * 2, c1 = c0 + 1;
    float a1k0[3], a1k1[3];
    float s0c = 0.f, s1c = 0.f;
    #pragma unroll
    for (int k = 0; k < 3; ++k) {
        a1k0[k] = a1s[c0 * 3 + k];  a1k1[k] = a1s[c1 * 3 + k];
        s0c += bbs[c0 * 3 + k];     s1c += bbs[c1 * 3 + k];
    }
    const float c3_0 = b1[c0] + s0c;
    const float c3_1 = b1[c1] + s1c;
    const float ca_0 = c3_0 - bbs[c0 * 3 + 0];   // t = 0
    const float ca_1 = c3_1 - bbs[c1 * 3 + 0];
    const float cb_0 = c3_0 - bbs[c0 * 3 + 2];   // t = 19
    const float cb_1 = c3_1 - bbs[c1 * 3 + 2];

    // efa-stage mapping: warp covers 8 pair-rows x 4 edges
    const int fpr = (w & 3) * 8 + (lane & 7);     // pair-row 0..31
    const int fe  = (w >> 2) * 4 + (lane >> 3);   // edge 0..7
    const int fh0 = (fpr >> 3) * 16 + (fpr & 7);
    const int fh1 = fh0 + 8;

    // prefetch first group's edge scalars
    float epref = 0.f;
    if (blockIdx.x < NGROUPS && tid < NE * TT)
        epref = ew[blockIdx.x * (NE * TT) + tid];

    for (int g = blockIdx.x; g < NGROUPS; g += gridDim.x) {
        const int m0 = g * NE;

        if (tid < NE * TT) e_s[tid] = epref;
        const int gn = g + gridDim.x;
        if (gn < NGROUPS && tid < NE * TT)
            epref = ew[gn * (NE * TT) + tid];
        __syncthreads();

        // ---- x1 = relu(folded conv1), packed bf16x2 by channel pair ----------
        {
            const float* ep = e_s + xe * TT;
            uint32_t* oa = xsu + prow * XR + xe * ESLOT + 1;
            #pragma unroll
            for (int t = 0; t < TT; ++t) {
                float x0, x1v;
                if (t == 0) {
                    x0 = ca_0 + a1k0[1] * ep[0] + a1k0[2] * ep[1];
                    x1v = ca_1 + a1k1[1] * ep[0] + a1k1[2] * ep[1];
                } else if (t == 19) {
                    x0 = cb_0 + a1k0[0] * ep[18] + a1k0[1] * ep[19];
                    x1v = cb_1 + a1k1[0] * ep[18] + a1k1[1] * ep[19];
                } else {
                    x0 = c3_0 + a1k0[0]*ep[t-1] + a1k0[1]*ep[t] + a1k0[2]*ep[t+1];
                    x1v = c3_1 + a1k1[0]*ep[t-1] + a1k1[1]*ep[t] + a1k1[2]*ep[t+1];
                }
                oa[t] = pkbf2(fmaxf(x0, 0.f), fmaxf(x1v, 0.f));
            }
        }
        __syncthreads();

        // ---- conv2 via bf16 MMA: warp = 32 h-rows x 5 q (B redundancy 2x) ----
        float d[5][8];
        #pragma unroll
        for (int q = 0; q < 5; ++q)
            #pragma unroll
            for (int j = 0; j < 8; ++j) d[q][j] = 0.f;

        #pragma unroll 2
        for (int kb = 0; kb < 12; ++kb) {
            const uint4 A0 = *(const uint4*)(w2f + ((ht0 * 12 + kb) * 32 + lane) * 4);
            const uint4 A1 = *(const uint4*)(w2f + ((ht1 * 12 + kb) * 32 + lane) * 4);
            const int rp = (kb & 3) * 8 + tig;
            const int koff = (kb >> 2) - 1;
            const uint32_t* bp = xsu + rp * XR + koff;
            #pragma unroll
            for (int q = 0; q < 5; ++q) {
                uint32_t b0 = bp[cq[q]];
                uint32_t b1 = bp[cq[q] + 4 * XR];
                mma_bf16(d[q] + 0, A0, b0, b1);
                mma_bf16(d[q] + 4, A1, b0, b1);
            }
        }
        __syncthreads();  // all B reads done before overwriting the tile

        // ---- epilogue: x2 = relu(d+b2) packed (r, r+8) -> pair-rows -----------
        {
            uint32_t* op0 = xsu + (ht0 * 8 + gid) * XR;
            uint32_t* op1 = xsu + (ht1 * 8 + gid) * XR;
            #pragma unroll
            for (int q = 0; q < 5; ++q) {
                op0[dc0[q]] = pkbf2(fmaxf(d[q][0] + b2v0, 0.f),
                                    fmaxf(d[q][2] + b2v1, 0.f));
                op0[dc1[q]] = pkbf2(fmaxf(d[q][1] + b2v0, 0.f),
                                    fmaxf(d[q][3] + b2v1, 0.f));
                op1[dc0[q]] = pkbf2(fmaxf(d[q][4] + b2v2, 0.f),
                                    fmaxf(d[q][6] + b2v3, 0.f));
                op1[dc1[q]] = pkbf2(fmaxf(d[q][5] + b2v2, 0.f),
                                    fmaxf(d[q][7] + b2v3, 0.f));
            }
        }
        __syncthreads();

        // ---- u_pre = Wt1^T @ x2 via bf16 MMA ----------------------------------
        float d2[5][8];
        #pragma unroll
        for (int q = 0; q < 5; ++q)
            #pragma unroll
            for (int j = 0; j < 8; ++j) d2[q][j] = 0.f;

        #pragma unroll
        for (int kb = 0; kb < 4; ++kb) {
            const uint4 A0 = *(const uint4*)(wt1f + ((ht0 * 4 + kb) * 32 + lane) * 4);
            const uint4 A1 = *(const uint4*)(wt1f + ((ht1 * 4 + kb) * 32 + lane) * 4);
            const uint32_t* bp = xsu + (kb * 8 + tig) * XR;
            #pragma unroll
            for (int q = 0; q < 5; ++q) {
                uint32_t b0 = bp[cq[q]];
                uint32_t b1 = bp[cq[q] + 4 * XR];
                mma_bf16(d2[q] + 0, A0, b0, b1);
                mma_bf16(d2[q] + 4, A1, b0, b1);
            }
        }

        // ---- score partials (indexed by column; 2 h-groups) -------------------
        #pragma unroll
        for (int q = 0; q < 5; ++q) {
            float s0 = tanha(d2[q][0] + bt1v0) * wt2v0
                     + tanha(d2[q][2] + bt1v1) * wt2v1
                     + tanha(d2[q][4] + bt1v2) * wt2v2
                     + tanha(d2[q][6] + bt1v3) * wt2v3;
            float s1 = tanha(d2[q][1] + bt1v0) * wt2v0
                     + tanha(d2[q][3] + bt1v1) * wt2v1
                     + tanha(d2[q][5] + bt1v2) * wt2v2
                     + tanha(d2[q][7] + bt1v3) * wt2v3;
            #pragma unroll
            for (int off = 4; off < 32; off <<= 1) {
                s0 += __shfl_xor_sync(0xffffffffu, s0, off);
                s1 += __shfl_xor_sync(0xffffffffu, s1, off);
            }
            if (lane < 4) {
                spart[hgrp * 176 + dc0[q]] = s0;
                spart[hgrp * 176 + dc1[q]] = s1;
            }
        }
        __syncthreads();

        // ---- temporal softmax: warp w handles edge w --------------------------
        {
            float v = -1e30f;
            if (lane < TT) {
                int col = w * ESLOT + 1 + lane;
                v = spart[col] + spart[176 + col] + bt2v;
            }
            float mx = v;
            #pragma unroll
            for (int off = 16; off; off >>= 1)
                mx = fmaxf(mx, __shfl_xor_sync(0xffffffffu, mx, off));
            float ev = (lane < TT) ? expf(v - mx) : 0.f;
            float sum = ev;
            #pragma unroll
            for (int off = 16; off; off >>= 1)
                sum += __shfl_xor_sync(0xffffffffu, sum, off);
            if (lane < TT) att_s[w * TT + lane] = ev / sum;
        }
        __syncthreads();

        // ---- efa: (pair-row, edge) per thread; unpack bf16x2 ------------------
        {
            const uint32_t* xr = xsu + fpr * XR + fe * ESLOT + 1;
            const float* at = att_s + fe * TT;
            float a0 = 0.f, a1 = 0.f;
            #pragma unroll
            for (int t = 0; t < TT; ++t) {
                uint32_t wd = xr[t];
                float av = at[t];
                a0 += bfu_lo(wd) * av;
                a1 += bfu_hi(wd) * av;
            }
            efa_s[fe * 68 + fh0] = a0;
            efa_s[fe * 68 + fh1] = a1;
            g_efa[(m0 + fe) * 64 + fh0] = a0;
            g_efa[(m0 + fe) * 64 + fh1] = a1;
        }
        __syncthreads();

        // ---- spatial score via tf32 MMA: D[64h x 8e], K = 64 ------------------
        if (w < 4) {
            const int ht2 = w;
            float d3[4] = {0.f, 0.f, 0.f, 0.f};
            #pragma unroll
            for (int kb = 0; kb < 8; ++kb) {
                const uint4 A = *(const uint4*)(ws1f + ((ht2 * 8 + kb) * 32 + lane) * 4);
                const float* bp = efa_s + gid * 68 + kb * 8 + tig;
                uint32_t b0 = __float_as_uint(bp[0]);
                uint32_t b1 = __float_as_uint(bp[4]);
                mma_tf32(d3, A, b0, b1);
            }
            const int rr0 = ht2 * 16 + gid;
            float v0 = tanha(d3[0] + bs1[rr0]) * Ws2[rr0]
                     + tanha(d3[2] + bs1[rr0 + 8]) * Ws2[rr0 + 8];
            float v1 = tanha(d3[1] + bs1[rr0]) * Ws2[rr0]
                     + tanha(d3[3] + bs1[rr0 + 8]) * Ws2[rr0 + 8];
            #pragma unroll
            for (int off = 4; off < 32; off <<= 1) {
                v0 += __shfl_xor_sync(0xffffffffu, v0, off);
                v1 += __shfl_xor_sync(0xffffffffu, v1, off);
            }
            if (lane < 4) {
                int e0 = lane * 2;
                ss2[ht2 * 8 + e0]     = v0;
                ss2[ht2 * 8 + e0 + 1] = v1;
            }
        }
        __syncthreads();
        if (tid < NE)
            g_score[m0 + tid] = ss2[tid] + ss2[8 + tid] + ss2[16 + tid]
                              + ss2[24 + tid] + bs2v;
    }
}

// ---------------------------------------------------------------------------
// K3: per-batch spatial softmax over N*N = 10000 scores
// ---------------------------------------------------------------------------
__global__ void __launch_bounds__(1024) k_spatial() {
    __shared__ float red[1024];
    __shared__ float mx_s, z_s;
    int b = blockIdx.x, tid = threadIdx.x;
    const float* sc = g_score + b * (NN * NN);

    float mx = -1e30f;
    for (int i = tid; i < NN * NN; i += 1024) mx = fmaxf(mx, sc[i]);
    red[tid] = mx;
    __syncthreads();
    for (int s = 512; s; s >>= 1) {
        if (tid < s) red[tid] = fmaxf(red[tid], red[tid + s]);
        __syncthreads();
    }
    if (tid == 0) mx_s = red[0];
    __syncthreads();
    float m = mx_s, z = 0.f;
    for (int i = tid; i < NN * NN; i += 1024) z += expf(sc[i] - m);
    red[tid] = z;
    __syncthreads();
    for (int s = 512; s; s >>= 1) {
        if (tid < s) red[tid] += red[tid + s];
        __syncthreads();
    }
    if (tid == 0) z_s = red[0];
    __syncthreads();
    float inv = 1.f / z_s;
    for (int i = tid; i < NN * NN; i += 1024)
        g_attw[b * (NN * NN) + i] = expf(sc[i] - m) * inv;
}

// ---------------------------------------------------------------------------
// K4: node aggregation + 3-layer MLP. One block per (b,i) node.
// ---------------------------------------------------------------------------
__global__ void __launch_bounds__(256) k_node(
    const float* __restrict__ Wg1, const float* __restrict__ bg1,
    const float* __restrict__ Wg2, const float* __restrict__ bg2,
    const float* __restrict__ Wout, const float* __restrict__ bout,
    float* __restrict__ out)
{
    __shared__ float nsm[256], g1s[64], g2s[64];
    const int bi = blockIdx.x;
    const int tid = threadIdx.x;
    const int h = tid & 63, quarter = tid >> 6;

    const float* efa = g_efa + (size_t)bi * NN * HH;
    const float* aw  = g_attw + bi * NN;
    float a = 0.f;
    #pragma unroll 5
    for (int j = quarter * 25; j < quarter * 25 + 25; ++j)
        a += efa[j * 64 + h] * aw[j];
    nsm[tid] = a;
    __syncthreads();
    if (tid < 64) {
        float s = nsm[tid] + nsm[tid + 64] + nsm[tid + 128] + nsm[tid + 192];
        nsm[tid] = s;
    }
    __syncthreads();
    if (tid < 64) {
        float acc = bg1[tid];
        for (int i = 0; i < 64; ++i) acc += nsm[i] * Wg1[i * 64 + tid];
        g1s[tid] = fmaxf(acc, 0.f);
    }
    __syncthreads();
    if (tid < 64) {
        float acc = bg2[tid];
        for (int i = 0; i < 64; ++i) acc += g1s[i] * Wg2[i * 64 + tid];
        g2s[tid] = fmaxf(acc, 0.f);
    }
    __syncthreads();
    if (tid < OO) {
        float acc = bout[tid];
        for (int i = 0; i < 64; ++i) acc += g2s[i] * Wout[i * OO + tid];
        out[bi * OO + tid] = fmaxf(acc, 0.f);
    }
}

// ---------------------------------------------------------------------------
extern "C" void kernel_launch(void* const* d_in, const int* in_sizes, int n_in,
                              void* d_out, int out_size) {
    const float* ew   = (const float*)d_in[0];
    const float* We   = (const float*)d_in[1];
    const float* be   = (const float*)d_in[2];
    const float* w1   = (const float*)d_in[3];
    const float* b1   = (const float*)d_in[4];
    const float* w2   = (const float*)d_in[5];
    const float* b2   = (const float*)d_in[6];
    const float* Wt1  = (const float*)d_in[7];
    const float* bt1  = (const float*)d_in[8];
    const float* Wt2  = (const float*)d_in[9];
    const float* bt2  = (const float*)d_in[10];
    const float* Ws1  = (const float*)d_in[11];
    const float* bs1  = (const float*)d_in[12];
    const float* Ws2  = (const float*)d_in[13];
    const float* bs2  = (const float*)d_in[14];
    const float* Wg1  = (const float*)d_in[15];
    const float* bg1  = (const float*)d_in[16];
    const float* Wg2  = (const float*)d_in[17];
    const float* bg2  = (const float*)d_in[18];
    const float* Wout = (const float*)d_in[19];
    const float* bout = (const float*)d_in[20];
    float* out = (float*)d_out;

    const int smem_bytes = S_TOTAL * 4;  // 81280 B per CTA
    cudaFuncSetAttribute(k_edge, cudaFuncAttributeMaxDynamicSharedMemorySize,
                         smem_bytes);

    k_edge<<<NBLOCKS, NTHREADS, smem_bytes>>>(ew, We, be, w1, b1, w2, b2,
                                              Wt1, bt1, Wt2, bt2,
                                              Ws1, bs1, Ws2, bs2);
    k_spatial<<<BB, 1024>>>();
    k_node<<<BB * NN, 256>>>(Wg1, bg1, Wg2, bg2, Wout, bout, out);
}